// round 12
// baseline (speedup 1.0000x reference)
#include <cuda_runtime.h>
#include <cmath>

// Problem constants
#define B_    4096
#define IN_   1024
#define F_    512
#define HID_  128
#define D_    128
#define RH_   64
#define C_    10
#define R_    16
#define CH_   1280   // C_*HID_
#define NSEG_ 8
#define CHSEG_ 160   // CH_/NSEG_
#define STG_  5      // cp.async pipeline stages
#define KW_SMEM_ ((2560 + STG_ * 4096) * 4)          // 92160 bytes
#define KOUT_SMEM_ ((16384 + 2 * 2064) * 4)          // 82048 bytes

// ---------------- device scratch ----------------
__device__ __align__(256) float g_rv[R_][D_];
__device__ __align__(256) float g_P[CH_][R_];            // P[ch][r] = w[r,c]*W2[r,h]
__device__ __align__(256) float g_WeffP[NSEG_][R_][F_];  // k_weff partials (incl. bias)
__device__ __align__(256) float g_WxT[IN_][R_];          // [i][r], atomic-accumulated
__device__ __align__(256) float g_cst[R_];               // beff + Weff·base_b (atomics)

// ---------------- helpers ----------------
__device__ __forceinline__ unsigned long long pk2(float a, float b) {
    unsigned long long r;
    asm("mov.b64 %0, {%1,%2};" : "=l"(r) : "f"(a), "f"(b));
    return r;
}
__device__ __forceinline__ void upk2(unsigned long long v, float& a, float& b) {
    asm("mov.b64 {%0,%1}, %2;" : "=f"(a), "=f"(b) : "l"(v));
}
#define FMA2(acc, a, b) asm("fma.rn.f32x2 %0, %1, %2, %0;" : "+l"(acc) : "l"(a), "l"(b))

__device__ __forceinline__ unsigned smem_u32(const void* p) {
    return (unsigned)__cvta_generic_to_shared(p);
}
__device__ __forceinline__ void cp16(unsigned dst, const void* src) {
    asm volatile("cp.async.cg.shared.global [%0], [%1], 16;" :: "r"(dst), "l"(src) : "memory");
}

// ============ k_head: fused w, r1, rv, W2, b1, beff->cst, P; zero WxT ============
__global__ void __launch_bounds__(256) k_head(
    const float* __restrict__ pref,
    const float* __restrict__ wm1_w, const float* __restrict__ wm1_b,
    const float* __restrict__ wm2_w, const float* __restrict__ wm2_b,
    const float* __restrict__ ray0_w, const float* __restrict__ ray0_b,
    const float* __restrict__ ray2_w, const float* __restrict__ ray2_b,
    const float* __restrict__ fc2_w, const float* __restrict__ fc2_b,
    const float* __restrict__ b1_w,  const float* __restrict__ b1_b,
    const float* __restrict__ b2_w,  const float* __restrict__ b2_b) {
    int r = blockIdx.x;
    int t = threadIdx.x;
    int warp = t >> 5, lane = t & 31;
    __shared__ float sh[16];
    __shared__ float sw[C_];
    __shared__ float sinv;
    __shared__ float sr1[RH_];
    __shared__ __align__(16) float srv[D_];
    __shared__ __align__(16) float sW2[HID_];
    __shared__ __align__(16) float sb1[HID_];
    __shared__ float sb0[HID_], sbb[HID_], sb2r[D_];

    // zero g_WxT for this call (graph replay safe)
    for (int z = r * 256 + t; z < IN_ * R_; z += 16 * 256)
        ((float*)g_WxT)[z] = 0.f;

    float p0 = __ldg(pref + 2 * r), p1 = __ldg(pref + 2 * r + 1);
    if (t < 16) {
        float a = p0 * __ldg(wm1_w + t * 2) + p1 * __ldg(wm1_w + t * 2 + 1) + __ldg(wm1_b + t);
        sh[t] = a > 0.f ? a : 0.f;
    }
    __syncthreads();
    if (t < C_) {
        float a = __ldg(wm2_b + t);
        #pragma unroll
        for (int j = 0; j < 16; j++) a += sh[j] * __ldg(wm2_w + t * 16 + j);
        sw[t] = 1.f / (1.f + expf(-a));
    }
    __syncthreads();
    if (t == 0) {
        float s = 0.f;
        #pragma unroll
        for (int c = 0; c < C_; c++) s += sw[c];
        sinv = 1.f / s;
    }
    __syncthreads();
    if (t < C_) sw[t] *= sinv;
    __syncthreads();

    if (t < RH_) {
        float a = 0.f;
        #pragma unroll
        for (int c = 0; c < C_; c++) {
            float2 rw = __ldg((const float2*)(ray0_w + (c * RH_ + t) * 2));
            a += sw[c] * (p0 * rw.x + p1 * rw.y + __ldg(ray0_b + c * RH_ + t));
        }
        sr1[t] = a > 0.f ? a : 0.f;
    } else if (t < 64 + D_) {
        int d = t - 64;
        float b = 0.f;
        #pragma unroll
        for (int c = 0; c < C_; c++) b += sw[c] * __ldg(ray2_b + c * D_ + d);
        sb2r[d] = b;
    }
    __syncthreads();

    // rv: 8 warps x 16 oi, lanes over h
    {
        float r1a = sr1[lane], r1b = sr1[lane + 32];
        float acc[16];
        #pragma unroll
        for (int oi = 0; oi < 16; oi++) acc[oi] = 0.f;
        #pragma unroll
        for (int c = 0; c < C_; c++) {
            float wc = sw[c];
            #pragma unroll
            for (int oi = 0; oi < 16; oi++) {
                int o = warp * 16 + oi;
                const float* row = ray2_w + ((size_t)(c * D_ + o)) * RH_;
                acc[oi] += wc * (__ldg(row + lane) * r1a + __ldg(row + lane + 32) * r1b);
            }
        }
        #pragma unroll
        for (int oi = 0; oi < 16; oi++) {
            float s = acc[oi];
            #pragma unroll
            for (int off = 16; off > 0; off >>= 1) s += __shfl_down_sync(0xffffffffu, s, off);
            if (lane == 0) {
                int o = warp * 16 + oi;
                float v = s + sb2r[o];
                srv[o] = v;
                g_rv[r][o] = v;
            }
        }
    }
    if (t < 128) {
        float b = 0.f;
        #pragma unroll
        for (int c = 0; c < C_; c++) b += sw[c] * __ldg(fc2_b + c * HID_ + t);
        sb0[t] = b;
    } else {
        int o = t - 128;
        float b = 0.f;
        #pragma unroll
        for (int c = 0; c < C_; c++) b += sw[c] * __ldg(b1_b + c * HID_ + o);
        sbb[o] = b;
    }
    __syncthreads();

    // W2 (warps 0-3) and b1 (warps 4-7): warp handles 32 o's
    {
        int kind = warp >> 2;
        int ob = (warp & 3) * 32;
        const float* Wc = kind ? b1_w : fc2_w;
        float4 rv4 = *(const float4*)&srv[lane * 4];
        float acc[32];
        #pragma unroll
        for (int oi = 0; oi < 32; oi++) acc[oi] = 0.f;
        #pragma unroll
        for (int c = 0; c < C_; c++) {
            float wc = sw[c];
            #pragma unroll
            for (int oi = 0; oi < 32; oi++) {
                int o = ob + oi;
                float4 v = __ldg((const float4*)(Wc + ((size_t)(c * HID_ + o)) * D_) + lane);
                acc[oi] += wc * (v.x * rv4.x + v.y * rv4.y + v.z * rv4.z + v.w * rv4.w);
            }
        }
        #pragma unroll
        for (int oi = 0; oi < 32; oi++) {
            float s = acc[oi];
            #pragma unroll
            for (int off = 16; off > 0; off >>= 1) s += __shfl_down_sync(0xffffffffu, s, off);
            if (lane == 0) {
                int o = ob + oi;
                if (kind) sb1[o] = s + sbb[o]; else sW2[o] = s + sb0[o];
            }
        }
    }
    __syncthreads();

    if (warp == 0) {
        float4 rv4 = *(const float4*)&srv[lane * 4];
        float acc = 0.f;
        #pragma unroll
        for (int c = 0; c < C_; c++) {
            float wc = sw[c];
            float4 bw = __ldg((const float4*)(b2_w + c * D_) + lane);
            acc += wc * (bw.x * rv4.x + bw.y * rv4.y + bw.z * rv4.z + bw.w * rv4.w);
            if (lane == 0) acc += wc * __ldg(b2_b + c);
        }
        float4 w24 = *(const float4*)&sW2[lane * 4];
        float4 b14 = *(const float4*)&sb1[lane * 4];
        acc += w24.x * b14.x + w24.y * b14.y + w24.z * b14.z + w24.w * b14.w;
        #pragma unroll
        for (int off = 16; off > 0; off >>= 1) acc += __shfl_down_sync(0xffffffffu, acc, off);
        if (lane == 0) g_cst[r] = acc;   // beff; k_wx atomically adds Weff·base_b
    }
    for (int ch = t; ch < CH_; ch += 256)
        g_P[ch][r] = sw[ch >> 7] * sW2[ch & 127];
}

// ============ k_weff v6: cp.async 5-stage pipeline, NO in-loop barriers ========
extern __shared__ float dsm_[];
__global__ void __launch_bounds__(256, 2) k_weff(const float* __restrict__ fc1_w,
                                                 const float* __restrict__ fc1_b) {
    float* sP   = dsm_;          // 2560 floats (160 ch x 16 r)
    float* sbuf = dsm_ + 2560;   // STG_ x 4096 floats (4 ch x 8 f x 128 d)
    int seg = blockIdx.y;
    int t = threadIdx.x;
    int warp = t >> 5, lane = t & 31;

    for (int idx = t; idx < CHSEG_ * 16; idx += 256)
        sP[idx] = ((const float*)g_P[seg * CHSEG_])[idx];

    const float4* gbase = (const float4*)fc1_w
        + (size_t)(seg * CHSEG_) * 16384u + (size_t)(blockIdx.x * 8 + warp) * 32u + lane;
    unsigned sbase = smem_u32(sbuf);
    unsigned my_off = (unsigned)((warp * 32 + lane) * 16);

    __syncthreads();   // sP visible to all warps (the ONLY cross-warp data)

    #pragma unroll
    for (int s = 0; s < STG_ - 1; s++) {
        #pragma unroll
        for (int q = 0; q < 4; q++) {
            cp16(sbase + (unsigned)s * 16384u + (unsigned)q * 4096u + my_off,
                 gbase + (size_t)(s * 4 + q) * 16384u);
        }
        asm volatile("cp.async.commit_group;" ::: "memory");
    }

    unsigned long long acc[4][8];
    #pragma unroll
    for (int j = 0; j < 4; j++)
        #pragma unroll
        for (int rp = 0; rp < 8; rp++) acc[j][rp] = 0ull;

    for (int i = 0; i < CHSEG_ / 4; i++) {
        asm volatile("cp.async.wait_group %0;" :: "n"(STG_ - 2) : "memory");
        const float* bufq = sbuf + (i % STG_) * 4096;
        #pragma unroll
        for (int q = 0; q < 4; q++) {
            float4 v = *(const float4*)(bufq + q * 1024 + warp * 128 + lane * 4);
            const ulonglong2* pp = (const ulonglong2*)(sP + (i * 4 + q) * 16);
            ulonglong2 pA = pp[0], pB = pp[1], pC = pp[2], pD = pp[3];
            unsigned long long u0 = pk2(v.x, v.x);
            unsigned long long u1 = pk2(v.y, v.y);
            unsigned long long u2 = pk2(v.z, v.z);
            unsigned long long u3 = pk2(v.w, v.w);
            FMA2(acc[0][0], u0, pA.x); FMA2(acc[0][1], u0, pA.y);
            FMA2(acc[0][2], u0, pB.x); FMA2(acc[0][3], u0, pB.y);
            FMA2(acc[0][4], u0, pC.x); FMA2(acc[0][5], u0, pC.y);
            FMA2(acc[0][6], u0, pD.x); FMA2(acc[0][7], u0, pD.y);
            FMA2(acc[1][0], u1, pA.x); FMA2(acc[1][1], u1, pA.y);
            FMA2(acc[1][2], u1, pB.x); FMA2(acc[1][3], u1, pB.y);
            FMA2(acc[1][4], u1, pC.x); FMA2(acc[1][5], u1, pC.y);
            FMA2(acc[1][6], u1, pD.x); FMA2(acc[1][7], u1, pD.y);
            FMA2(acc[2][0], u2, pA.x); FMA2(acc[2][1], u2, pA.y);
            FMA2(acc[2][2], u2, pB.x); FMA2(acc[2][3], u2, pB.y);
            FMA2(acc[2][4], u2, pC.x); FMA2(acc[2][5], u2, pC.y);
            FMA2(acc[2][6], u2, pD.x); FMA2(acc[2][7], u2, pD.y);
            FMA2(acc[3][0], u3, pA.x); FMA2(acc[3][1], u3, pA.y);
            FMA2(acc[3][2], u3, pB.x); FMA2(acc[3][3], u3, pB.y);
            FMA2(acc[3][4], u3, pC.x); FMA2(acc[3][5], u3, pC.y);
            FMA2(acc[3][6], u3, pD.x); FMA2(acc[3][7], u3, pD.y);
        }
        int s = i + STG_ - 1;
        if (s < CHSEG_ / 4) {
            unsigned slot = (unsigned)(s % STG_);
            #pragma unroll
            for (int q = 0; q < 4; q++) {
                cp16(sbase + slot * 16384u + (unsigned)q * 4096u + my_off,
                     gbase + (size_t)(s * 4 + q) * 16384u);
            }
        }
        asm volatile("cp.async.commit_group;" ::: "memory");
    }
    asm volatile("cp.async.wait_group 0;" ::: "memory");

    // fused fc1_b bias: lane covers ch = lane, lane+32, ... (5 iters)
    int f = blockIdx.x * 8 + warp;
    unsigned long long bacc[8];
    #pragma unroll
    for (int rp = 0; rp < 8; rp++) bacc[rp] = 0ull;
    #pragma unroll
    for (int it = 0; it < CHSEG_ / 32; it++) {
        int chl = it * 32 + lane;
        float bv = __ldg(fc1_b + (size_t)(seg * CHSEG_ + chl) * 512u + f);
        unsigned long long vv = pk2(bv, bv);
        const ulonglong2* pp = (const ulonglong2*)(sP + chl * 16);
        ulonglong2 pA = pp[0], pB = pp[1], pC = pp[2], pD = pp[3];
        FMA2(bacc[0], vv, pA.x); FMA2(bacc[1], vv, pA.y);
        FMA2(bacc[2], vv, pB.x); FMA2(bacc[3], vv, pB.y);
        FMA2(bacc[4], vv, pC.x); FMA2(bacc[5], vv, pC.y);
        FMA2(bacc[6], vv, pD.x); FMA2(bacc[7], vv, pD.y);
    }

    int d0 = lane * 4;
    float accr[16];
    #pragma unroll
    for (int rp = 0; rp < 8; rp++) {
        float a0, a1; upk2(bacc[rp], a0, a1);
        accr[2 * rp] = a0; accr[2 * rp + 1] = a1;
    }
    #pragma unroll
    for (int j = 0; j < 4; j++) {
        #pragma unroll
        for (int rp = 0; rp < 8; rp++) {
            float a0, a1; upk2(acc[j][rp], a0, a1);
            accr[2 * rp]     += a0 * g_rv[2 * rp][d0 + j];
            accr[2 * rp + 1] += a1 * g_rv[2 * rp + 1][d0 + j];
        }
    }
    #pragma unroll
    for (int off = 16; off > 0; off >>= 1)
        #pragma unroll
        for (int r = 0; r < 16; r++)
            accr[r] += __shfl_down_sync(0xffffffffu, accr[r], off);
    if (lane == 0) {
        #pragma unroll
        for (int r = 0; r < 16; r++) g_WeffP[seg][r][f] = accr[r];
    }
}

// ============ k_wx: sum 8 planes -> fold base_w -> atomic Wx; cst inline ======
__global__ void __launch_bounds__(128) k_wx(const float* __restrict__ base_w,
                                            const float* __restrict__ base_b) {
    __shared__ __align__(16) float sW[32][16];
    int t = threadIdx.x;
    int f0 = blockIdx.y * 32;
    for (int idx = t; idx < 32 * 16; idx += 128) {
        int ff = idx >> 4, r = idx & 15;
        float s = 0.f;
        #pragma unroll
        for (int sg = 0; sg < NSEG_; sg++) s += g_WeffP[sg][r][f0 + ff];
        sW[ff][r] = s;
    }
    __syncthreads();
    if (blockIdx.x == 0) {
        int r = t >> 3, fq = (t & 7) * 4;
        float p = 0.f;
        #pragma unroll
        for (int j = 0; j < 4; j++) p += sW[fq + j][r] * __ldg(base_b + f0 + fq + j);
        atomicAdd(&g_cst[r], p);
    }
    int i = blockIdx.x * 128 + t;
    unsigned long long acc[8];
    #pragma unroll
    for (int rp = 0; rp < 8; rp++) acc[rp] = 0ull;
    #pragma unroll 4
    for (int ff = 0; ff < 32; ff++) {
        float bw = __ldg(base_w + (size_t)(f0 + ff) * IN_ + i);
        unsigned long long b2 = pk2(bw, bw);
        const unsigned long long* pw = (const unsigned long long*)sW[ff];
        #pragma unroll
        for (int rp = 0; rp < 8; rp++) {
            unsigned long long tt = pw[rp];
            FMA2(acc[rp], b2, tt);
        }
    }
    #pragma unroll
    for (int rp = 0; rp < 8; rp++) {
        float a, b; upk2(acc[rp], a, b);
        atomicAdd(&g_WxT[i][2 * rp], a);
        atomicAdd(&g_WxT[i][2 * rp + 1], b);
    }
}

// ============ k_out v5: full-WxT smem + double-buffered x; 1 sync/chunk ========
extern __shared__ float osm_[];
__global__ void __launch_bounds__(256) k_out(const float* __restrict__ x,
                                             float* __restrict__ out, int write_raw) {
    float* swt = osm_;                  // [1024][16] = 16384 floats
    float* sxa = osm_ + 16384;          // [16][129] = 2064 floats
    float* sxb = sxa + 2064;
    __shared__ float sp[16][16][17];
    int t = threadIdx.x;
    int bl = t & 15, part = t >> 4;
    int bbase = blockIdx.x * 16;

    // stage full WxT (coalesced float4; L2-resident)
    #pragma unroll
    for (int k = 0; k < 16; k++)
        ((float4*)swt)[k * 256 + t] = ((const float4*)g_WxT)[k * 256 + t];
    // stage x chunk 0
    for (int idx = t; idx < 16 * 128; idx += 256) {
        int b = idx >> 7, i = idx & 127;
        sxa[b * 129 + i] = __ldg(x + (size_t)(bbase + b) * IN_ + i);
    }
    __syncthreads();

    unsigned long long acc[8];
    #pragma unroll
    for (int rp = 0; rp < 8; rp++) acc[rp] = 0ull;

    for (int c = 0; c < 8; c++) {
        const float* cur = (c & 1) ? sxb : sxa;
        float* nxt = (c & 1) ? sxa : sxb;
        if (c < 7) {
            int i0n = (c + 1) * 128;
            for (int idx = t; idx < 16 * 128; idx += 256) {
                int b = idx >> 7, i = idx & 127;
                nxt[b * 129 + i] = __ldg(x + (size_t)(bbase + b) * IN_ + i0n + i);
            }
        }
        int i0 = c * 128;
        #pragma unroll
        for (int ii = 0; ii < 8; ii++) {
            int il = part * 8 + ii;
            float xv = cur[bl * 129 + il];
            unsigned long long ux = pk2(xv, xv);
            const ulonglong2* w = (const ulonglong2*)(swt + (size_t)(i0 + il) * 16);
            ulonglong2 wA = w[0], wB = w[1], wC = w[2], wD = w[3];
            FMA2(acc[0], ux, wA.x); FMA2(acc[1], ux, wA.y);
            FMA2(acc[2], ux, wB.x); FMA2(acc[3], ux, wB.y);
            FMA2(acc[4], ux, wC.x); FMA2(acc[5], ux, wC.y);
            FMA2(acc[6], ux, wD.x); FMA2(acc[7], ux, wD.y);
        }
        __syncthreads();
    }

    #pragma unroll
    for (int rp = 0; rp < 8; rp++) {
        float a, b; upk2(acc[rp], a, b);
        sp[part][bl][2 * rp] = a;
        sp[part][bl][2 * rp + 1] = b;
    }
    __syncthreads();

    int b = t >> 4, r = t & 15;
    float s = 0.f;
    #pragma unroll
    for (int p = 0; p < 16; p++) s += sp[p][b][r];
    float v = s + g_cst[r];
    out[r * B_ + bbase + b] = 1.f / (1.f + expf(-v));
    if (write_raw) out[R_ * B_ + r * B_ + bbase + b] = v;
}

// ---------------- launcher ----------------
extern "C" void kernel_launch(void* const* d_in, const int* in_sizes, int n_in,
                              void* d_out, int out_size) {
    const float* x      = (const float*)d_in[0];
    const float* pref   = (const float*)d_in[1];
    const float* base_w = (const float*)d_in[2];
    const float* base_b = (const float*)d_in[3];
    const float* wm1_w  = (const float*)d_in[4];
    const float* wm1_b  = (const float*)d_in[5];
    const float* wm2_w  = (const float*)d_in[6];
    const float* wm2_b  = (const float*)d_in[7];
    const float* ray0_w = (const float*)d_in[8];
    const float* ray0_b = (const float*)d_in[9];
    const float* ray2_w = (const float*)d_in[10];
    const float* ray2_b = (const float*)d_in[11];
    const float* fc1_w  = (const float*)d_in[12];
    const float* fc1_b  = (const float*)d_in[13];
    const float* b1_w   = (const float*)d_in[14];
    const float* b1_b   = (const float*)d_in[15];
    const float* fc2_w  = (const float*)d_in[16];
    const float* fc2_b  = (const float*)d_in[17];
    const float* b2_w   = (const float*)d_in[18];
    const float* b2_b   = (const float*)d_in[19];
    float* out = (float*)d_out;
    int write_raw = (out_size >= 2 * R_ * B_) ? 1 : 0;

    cudaFuncSetAttribute(k_weff, cudaFuncAttributeMaxDynamicSharedMemorySize, KW_SMEM_);
    cudaFuncSetAttribute(k_out, cudaFuncAttributeMaxDynamicSharedMemorySize, KOUT_SMEM_);

    k_head<<<R_, 256>>>(pref, wm1_w, wm1_b, wm2_w, wm2_b,
                        ray0_w, ray0_b, ray2_w, ray2_b,
                        fc2_w, fc2_b, b1_w, b1_b, b2_w, b2_b);
    k_weff<<<dim3(F_ / 8, NSEG_), 256, KW_SMEM_>>>(fc1_w, fc1_b);
    k_wx<<<dim3(8, 16), 128>>>(base_w, base_b);
    k_out<<<B_ / 16, 256, KOUT_SMEM_>>>(x, out, write_raw);   // #4 -> profiled
}

// round 13
// speedup vs baseline: 1.1019x; 1.1019x over previous
#include <cuda_runtime.h>
#include <cmath>

// Problem constants
#define B_    4096
#define IN_   1024
#define F_    512
#define HID_  128
#define D_    128
#define RH_   64
#define C_    10
#define R_    16
#define CH_   1280   // C_*HID_
#define NSEG_ 8
#define CHSEG_ 160   // CH_/NSEG_
#define STG_  5      // cp.async pipeline stages
#define KW_SMEM_ ((2560 + STG_ * 4096) * 4)   // 92160 bytes

// ---------------- device scratch ----------------
__device__ __align__(256) float g_rv[R_][D_];
__device__ __align__(256) float g_P[CH_][R_];            // P[ch][r] = w[r,c]*W2[r,h]
__device__ __align__(256) float g_WeffP[NSEG_][R_][F_];  // k_weff partials (incl. bias)
__device__ __align__(256) float g_WxT[IN_][R_];          // [i][r], atomic-accumulated
__device__ __align__(256) float g_cst[R_];               // beff + Weff·base_b (atomics)

// ---------------- helpers ----------------
__device__ __forceinline__ unsigned long long pk2(float a, float b) {
    unsigned long long r;
    asm("mov.b64 %0, {%1,%2};" : "=l"(r) : "f"(a), "f"(b));
    return r;
}
__device__ __forceinline__ void upk2(unsigned long long v, float& a, float& b) {
    asm("mov.b64 {%0,%1}, %2;" : "=f"(a), "=f"(b) : "l"(v));
}
#define FMA2(acc, a, b) asm("fma.rn.f32x2 %0, %1, %2, %0;" : "+l"(acc) : "l"(a), "l"(b))

__device__ __forceinline__ unsigned smem_u32(const void* p) {
    return (unsigned)__cvta_generic_to_shared(p);
}
__device__ __forceinline__ void cp16(unsigned dst, const void* src) {
    asm volatile("cp.async.cg.shared.global [%0], [%1], 16;" :: "r"(dst), "l"(src) : "memory");
}

// ============ k_head: fused w, r1, rv, W2, b1, beff->cst, P; zero WxT ============
__global__ void __launch_bounds__(256) k_head(
    const float* __restrict__ pref,
    const float* __restrict__ wm1_w, const float* __restrict__ wm1_b,
    const float* __restrict__ wm2_w, const float* __restrict__ wm2_b,
    const float* __restrict__ ray0_w, const float* __restrict__ ray0_b,
    const float* __restrict__ ray2_w, const float* __restrict__ ray2_b,
    const float* __restrict__ fc2_w, const float* __restrict__ fc2_b,
    const float* __restrict__ b1_w,  const float* __restrict__ b1_b,
    const float* __restrict__ b2_w,  const float* __restrict__ b2_b) {
    int r = blockIdx.x;
    int t = threadIdx.x;
    int warp = t >> 5, lane = t & 31;
    __shared__ float sh[16];
    __shared__ float sw[C_];
    __shared__ float sinv;
    __shared__ float sr1[RH_];
    __shared__ __align__(16) float srv[D_];
    __shared__ __align__(16) float sW2[HID_];
    __shared__ __align__(16) float sb1[HID_];
    __shared__ float sb0[HID_], sbb[HID_], sb2r[D_];

    // zero g_WxT for this call (graph replay safe)
    for (int z = r * 256 + t; z < IN_ * R_; z += 16 * 256)
        ((float*)g_WxT)[z] = 0.f;

    float p0 = __ldg(pref + 2 * r), p1 = __ldg(pref + 2 * r + 1);
    if (t < 16) {
        float a = p0 * __ldg(wm1_w + t * 2) + p1 * __ldg(wm1_w + t * 2 + 1) + __ldg(wm1_b + t);
        sh[t] = a > 0.f ? a : 0.f;
    }
    __syncthreads();
    if (t < C_) {
        float a = __ldg(wm2_b + t);
        #pragma unroll
        for (int j = 0; j < 16; j++) a += sh[j] * __ldg(wm2_w + t * 16 + j);
        sw[t] = 1.f / (1.f + expf(-a));
    }
    __syncthreads();
    if (t == 0) {
        float s = 0.f;
        #pragma unroll
        for (int c = 0; c < C_; c++) s += sw[c];
        sinv = 1.f / s;
    }
    __syncthreads();
    if (t < C_) sw[t] *= sinv;
    __syncthreads();

    if (t < RH_) {
        float a = 0.f;
        #pragma unroll
        for (int c = 0; c < C_; c++) {
            float2 rw = __ldg((const float2*)(ray0_w + (c * RH_ + t) * 2));
            a += sw[c] * (p0 * rw.x + p1 * rw.y + __ldg(ray0_b + c * RH_ + t));
        }
        sr1[t] = a > 0.f ? a : 0.f;
    } else if (t < 64 + D_) {
        int d = t - 64;
        float b = 0.f;
        #pragma unroll
        for (int c = 0; c < C_; c++) b += sw[c] * __ldg(ray2_b + c * D_ + d);
        sb2r[d] = b;
    }
    __syncthreads();

    // rv: 8 warps x 16 oi, lanes over h
    {
        float r1a = sr1[lane], r1b = sr1[lane + 32];
        float acc[16];
        #pragma unroll
        for (int oi = 0; oi < 16; oi++) acc[oi] = 0.f;
        #pragma unroll
        for (int c = 0; c < C_; c++) {
            float wc = sw[c];
            #pragma unroll
            for (int oi = 0; oi < 16; oi++) {
                int o = warp * 16 + oi;
                const float* row = ray2_w + ((size_t)(c * D_ + o)) * RH_;
                acc[oi] += wc * (__ldg(row + lane) * r1a + __ldg(row + lane + 32) * r1b);
            }
        }
        #pragma unroll
        for (int oi = 0; oi < 16; oi++) {
            float s = acc[oi];
            #pragma unroll
            for (int off = 16; off > 0; off >>= 1) s += __shfl_down_sync(0xffffffffu, s, off);
            if (lane == 0) {
                int o = warp * 16 + oi;
                float v = s + sb2r[o];
                srv[o] = v;
                g_rv[r][o] = v;
            }
        }
    }
    if (t < 128) {
        float b = 0.f;
        #pragma unroll
        for (int c = 0; c < C_; c++) b += sw[c] * __ldg(fc2_b + c * HID_ + t);
        sb0[t] = b;
    } else {
        int o = t - 128;
        float b = 0.f;
        #pragma unroll
        for (int c = 0; c < C_; c++) b += sw[c] * __ldg(b1_b + c * HID_ + o);
        sbb[o] = b;
    }
    __syncthreads();

    // W2 (warps 0-3) and b1 (warps 4-7): warp handles 32 o's
    {
        int kind = warp >> 2;
        int ob = (warp & 3) * 32;
        const float* Wc = kind ? b1_w : fc2_w;
        float4 rv4 = *(const float4*)&srv[lane * 4];
        float acc[32];
        #pragma unroll
        for (int oi = 0; oi < 32; oi++) acc[oi] = 0.f;
        #pragma unroll
        for (int c = 0; c < C_; c++) {
            float wc = sw[c];
            #pragma unroll
            for (int oi = 0; oi < 32; oi++) {
                int o = ob + oi;
                float4 v = __ldg((const float4*)(Wc + ((size_t)(c * HID_ + o)) * D_) + lane);
                acc[oi] += wc * (v.x * rv4.x + v.y * rv4.y + v.z * rv4.z + v.w * rv4.w);
            }
        }
        #pragma unroll
        for (int oi = 0; oi < 32; oi++) {
            float s = acc[oi];
            #pragma unroll
            for (int off = 16; off > 0; off >>= 1) s += __shfl_down_sync(0xffffffffu, s, off);
            if (lane == 0) {
                int o = ob + oi;
                if (kind) sb1[o] = s + sbb[o]; else sW2[o] = s + sb0[o];
            }
        }
    }
    __syncthreads();

    if (warp == 0) {
        float4 rv4 = *(const float4*)&srv[lane * 4];
        float acc = 0.f;
        #pragma unroll
        for (int c = 0; c < C_; c++) {
            float wc = sw[c];
            float4 bw = __ldg((const float4*)(b2_w + c * D_) + lane);
            acc += wc * (bw.x * rv4.x + bw.y * rv4.y + bw.z * rv4.z + bw.w * rv4.w);
            if (lane == 0) acc += wc * __ldg(b2_b + c);
        }
        float4 w24 = *(const float4*)&sW2[lane * 4];
        float4 b14 = *(const float4*)&sb1[lane * 4];
        acc += w24.x * b14.x + w24.y * b14.y + w24.z * b14.z + w24.w * b14.w;
        #pragma unroll
        for (int off = 16; off > 0; off >>= 1) acc += __shfl_down_sync(0xffffffffu, acc, off);
        if (lane == 0) g_cst[r] = acc;   // beff; k_wx atomically adds Weff·base_b
    }
    for (int ch = t; ch < CH_; ch += 256)
        g_P[ch][r] = sw[ch >> 7] * sW2[ch & 127];
}

// ============ k_weff v7: cp.async pipeline, strength-reduced addressing ========
// Unrolled by STG_ so consume/prefetch slots are compile-time; one running
// global pointer (+65536 float4/iter) and one running sP pointer (+16 u2/iter).
extern __shared__ float dsm_[];
__global__ void __launch_bounds__(256, 2) k_weff(const float* __restrict__ fc1_w,
                                                 const float* __restrict__ fc1_b) {
    float* sP   = dsm_;          // 2560 floats (160 ch x 16 r)
    float* sbuf = dsm_ + 2560;   // STG_ x 4096 floats (4 ch x 8 f x 128 d)
    int seg = blockIdx.y;
    int t = threadIdx.x;
    int warp = t >> 5, lane = t & 31;

    for (int idx = t; idx < CHSEG_ * 16; idx += 256)
        sP[idx] = ((const float*)g_P[seg * CHSEG_])[idx];

    const float4* gbase = (const float4*)fc1_w
        + (size_t)(seg * CHSEG_) * 16384u + (size_t)(blockIdx.x * 8 + warp) * 32u + lane;
    unsigned dstbase = smem_u32(sbuf) + (unsigned)((warp * 32 + lane) * 16);
    const float4* myb = (const float4*)sbuf + (warp * 32 + lane);  // + slot*1024 + q*256

    __syncthreads();   // sP visible to all warps (the ONLY cross-warp data)

    // prologue: issue stages 0..STG_-2 (per-warp groups)
    #pragma unroll
    for (int s = 0; s < STG_ - 1; s++) {
        #pragma unroll
        for (int q = 0; q < 4; q++)
            cp16(dstbase + (unsigned)(s * 16384 + q * 4096),
                 gbase + (size_t)(s * 4 + q) * 16384u);
        asm volatile("cp.async.commit_group;" ::: "memory");
    }

    unsigned long long acc[4][8];
    #pragma unroll
    for (int j = 0; j < 4; j++)
        #pragma unroll
        for (int rp = 0; rp < 8; rp++) acc[j][rp] = 0ull;

    const float4* gpre = gbase + (size_t)(STG_ - 1) * 4 * 16384u;
    const ulonglong2* pPtr = (const ulonglong2*)sP;

    #pragma unroll 1
    for (int g = 0; g < (CHSEG_ / 4) / STG_; g++) {   // 8 outer groups
        #pragma unroll
        for (int j5 = 0; j5 < STG_; j5++) {           // slot = j5 (compile-time)
            int i = g * STG_ + j5;
            asm volatile("cp.async.wait_group %0;" :: "n"(STG_ - 2) : "memory");
            const float4* bq = myb + j5 * 1024;
            #pragma unroll
            for (int q = 0; q < 4; q++) {
                float4 v = bq[q * 256];
                ulonglong2 pA = pPtr[q * 4 + 0], pB = pPtr[q * 4 + 1];
                ulonglong2 pC = pPtr[q * 4 + 2], pD = pPtr[q * 4 + 3];
                unsigned long long u0 = pk2(v.x, v.x);
                unsigned long long u1 = pk2(v.y, v.y);
                unsigned long long u2 = pk2(v.z, v.z);
                unsigned long long u3 = pk2(v.w, v.w);
                FMA2(acc[0][0], u0, pA.x); FMA2(acc[0][1], u0, pA.y);
                FMA2(acc[0][2], u0, pB.x); FMA2(acc[0][3], u0, pB.y);
                FMA2(acc[0][4], u0, pC.x); FMA2(acc[0][5], u0, pC.y);
                FMA2(acc[0][6], u0, pD.x); FMA2(acc[0][7], u0, pD.y);
                FMA2(acc[1][0], u1, pA.x); FMA2(acc[1][1], u1, pA.y);
                FMA2(acc[1][2], u1, pB.x); FMA2(acc[1][3], u1, pB.y);
                FMA2(acc[1][4], u1, pC.x); FMA2(acc[1][5], u1, pC.y);
                FMA2(acc[1][6], u1, pD.x); FMA2(acc[1][7], u1, pD.y);
                FMA2(acc[2][0], u2, pA.x); FMA2(acc[2][1], u2, pA.y);
                FMA2(acc[2][2], u2, pB.x); FMA2(acc[2][3], u2, pB.y);
                FMA2(acc[2][4], u2, pC.x); FMA2(acc[2][5], u2, pC.y);
                FMA2(acc[2][6], u2, pD.x); FMA2(acc[2][7], u2, pD.y);
                FMA2(acc[3][0], u3, pA.x); FMA2(acc[3][1], u3, pA.y);
                FMA2(acc[3][2], u3, pB.x); FMA2(acc[3][3], u3, pB.y);
                FMA2(acc[3][4], u3, pC.x); FMA2(acc[3][5], u3, pC.y);
                FMA2(acc[3][6], u3, pD.x); FMA2(acc[3][7], u3, pD.y);
            }
            pPtr += 16;
            if (i < (CHSEG_ / 4) - (STG_ - 1)) {
                const unsigned pslot = (unsigned)(((j5 + STG_ - 1) % STG_) * 16384);
                #pragma unroll
                for (int q = 0; q < 4; q++)
                    cp16(dstbase + pslot + (unsigned)(q * 4096), gpre + q * 16384);
            }
            gpre += 65536;
            asm volatile("cp.async.commit_group;" ::: "memory");
        }
    }
    asm volatile("cp.async.wait_group 0;" ::: "memory");

    // fused fc1_b bias: lane covers ch = lane, lane+32, ... (5 iters)
    int f = blockIdx.x * 8 + warp;
    unsigned long long bacc[8];
    #pragma unroll
    for (int rp = 0; rp < 8; rp++) bacc[rp] = 0ull;
    #pragma unroll
    for (int it = 0; it < CHSEG_ / 32; it++) {
        int chl = it * 32 + lane;
        float bv = __ldg(fc1_b + (size_t)(seg * CHSEG_ + chl) * 512u + f);
        unsigned long long vv = pk2(bv, bv);
        const ulonglong2* pp = (const ulonglong2*)(sP + chl * 16);
        ulonglong2 pA = pp[0], pB = pp[1], pC = pp[2], pD = pp[3];
        FMA2(bacc[0], vv, pA.x); FMA2(bacc[1], vv, pA.y);
        FMA2(bacc[2], vv, pB.x); FMA2(bacc[3], vv, pB.y);
        FMA2(bacc[4], vv, pC.x); FMA2(bacc[5], vv, pC.y);
        FMA2(bacc[6], vv, pD.x); FMA2(bacc[7], vv, pD.y);
    }

    int d0 = lane * 4;
    float accr[16];
    #pragma unroll
    for (int rp = 0; rp < 8; rp++) {
        float a0, a1; upk2(bacc[rp], a0, a1);
        accr[2 * rp] = a0; accr[2 * rp + 1] = a1;
    }
    #pragma unroll
    for (int j = 0; j < 4; j++) {
        #pragma unroll
        for (int rp = 0; rp < 8; rp++) {
            float a0, a1; upk2(acc[j][rp], a0, a1);
            accr[2 * rp]     += a0 * g_rv[2 * rp][d0 + j];
            accr[2 * rp + 1] += a1 * g_rv[2 * rp + 1][d0 + j];
        }
    }
    #pragma unroll
    for (int off = 16; off > 0; off >>= 1)
        #pragma unroll
        for (int r = 0; r < 16; r++)
            accr[r] += __shfl_down_sync(0xffffffffu, accr[r], off);
    if (lane == 0) {
        #pragma unroll
        for (int r = 0; r < 16; r++) g_WeffP[seg][r][f] = accr[r];
    }
}

// ============ k_wx: sum 8 planes -> fold base_w -> atomic Wx; cst inline ======
__global__ void __launch_bounds__(128) k_wx(const float* __restrict__ base_w,
                                            const float* __restrict__ base_b) {
    __shared__ __align__(16) float sW[32][16];
    int t = threadIdx.x;
    int f0 = blockIdx.y * 32;
    for (int idx = t; idx < 32 * 16; idx += 128) {
        int ff = idx >> 4, r = idx & 15;
        float s = 0.f;
        #pragma unroll
        for (int sg = 0; sg < NSEG_; sg++) s += g_WeffP[sg][r][f0 + ff];
        sW[ff][r] = s;
    }
    __syncthreads();
    if (blockIdx.x == 0) {
        int r = t >> 3, fq = (t & 7) * 4;
        float p = 0.f;
        #pragma unroll
        for (int j = 0; j < 4; j++) p += sW[fq + j][r] * __ldg(base_b + f0 + fq + j);
        atomicAdd(&g_cst[r], p);
    }
    int i = blockIdx.x * 128 + t;
    unsigned long long acc[8];
    #pragma unroll
    for (int rp = 0; rp < 8; rp++) acc[rp] = 0ull;
    #pragma unroll 4
    for (int ff = 0; ff < 32; ff++) {
        float bw = __ldg(base_w + (size_t)(f0 + ff) * IN_ + i);
        unsigned long long b2 = pk2(bw, bw);
        const unsigned long long* pw = (const unsigned long long*)sW[ff];
        #pragma unroll
        for (int rp = 0; rp < 8; rp++) {
            unsigned long long tt = pw[rp];
            FMA2(acc[rp], b2, tt);
        }
    }
    #pragma unroll
    for (int rp = 0; rp < 8; rp++) {
        float a, b; upk2(acc[rp], a, b);
        atomicAdd(&g_WxT[i][2 * rp], a);
        atomicAdd(&g_WxT[i][2 * rp + 1], b);
    }
}

// ============ k_out v4 (reverted, measured 16.5us): 16-b blocks, grid 256 ======
__global__ void __launch_bounds__(256) k_out(const float* __restrict__ x,
                                             float* __restrict__ out, int write_raw) {
    __shared__ float sx[16][129];
    __shared__ __align__(16) float swt[128][16];
    __shared__ float sp[16][16][17];
    int t = threadIdx.x;
    int bl = t & 15, part = t >> 4;
    int bbase = blockIdx.x * 16;

    unsigned long long acc[8];
    #pragma unroll
    for (int rp = 0; rp < 8; rp++) acc[rp] = 0ull;

    for (int c = 0; c < 8; c++) {
        int i0 = c * 128;
        #pragma unroll
        for (int idx = t; idx < 16 * 128; idx += 256) {
            int b = idx >> 7, i = idx & 127;
            sx[b][i] = __ldg(x + (size_t)(bbase + b) * IN_ + i0 + i);
        }
        #pragma unroll
        for (int idx = t; idx < 128 * 16; idx += 256)
            ((float*)swt)[idx] = ((const float*)g_WxT)[i0 * 16 + idx];
        __syncthreads();

        #pragma unroll
        for (int ii = 0; ii < 8; ii++) {
            int i = part * 8 + ii;
            float xv = sx[bl][i];
            unsigned long long ux = pk2(xv, xv);
            const ulonglong2* w = (const ulonglong2*)swt[i];
            ulonglong2 wA = w[0], wB = w[1], wC = w[2], wD = w[3];
            FMA2(acc[0], ux, wA.x); FMA2(acc[1], ux, wA.y);
            FMA2(acc[2], ux, wB.x); FMA2(acc[3], ux, wB.y);
            FMA2(acc[4], ux, wC.x); FMA2(acc[5], ux, wC.y);
            FMA2(acc[6], ux, wD.x); FMA2(acc[7], ux, wD.y);
        }
        __syncthreads();
    }

    #pragma unroll
    for (int rp = 0; rp < 8; rp++) {
        float a, b; upk2(acc[rp], a, b);
        sp[part][bl][2 * rp] = a;
        sp[part][bl][2 * rp + 1] = b;
    }
    __syncthreads();

    int b = t >> 4, r = t & 15;
    float s = 0.f;
    #pragma unroll
    for (int p = 0; p < 16; p++) s += sp[p][b][r];
    float v = s + g_cst[r];
    out[r * B_ + bbase + b] = 1.f / (1.f + expf(-v));
    if (write_raw) out[R_ * B_ + r * B_ + bbase + b] = v;
}

// ---------------- launcher ----------------
extern "C" void kernel_launch(void* const* d_in, const int* in_sizes, int n_in,
                              void* d_out, int out_size) {
    const float* x      = (const float*)d_in[0];
    const float* pref   = (const float*)d_in[1];
    const float* base_w = (const float*)d_in[2];
    const float* base_b = (const float*)d_in[3];
    const float* wm1_w  = (const float*)d_in[4];
    const float* wm1_b  = (const float*)d_in[5];
    const float* wm2_w  = (const float*)d_in[6];
    const float* wm2_b  = (const float*)d_in[7];
    const float* ray0_w = (const float*)d_in[8];
    const float* ray0_b = (const float*)d_in[9];
    const float* ray2_w = (const float*)d_in[10];
    const float* ray2_b = (const float*)d_in[11];
    const float* fc1_w  = (const float*)d_in[12];
    const float* fc1_b  = (const float*)d_in[13];
    const float* b1_w   = (const float*)d_in[14];
    const float* b1_b   = (const float*)d_in[15];
    const float* fc2_w  = (const float*)d_in[16];
    const float* fc2_b  = (const float*)d_in[17];
    const float* b2_w   = (const float*)d_in[18];
    const float* b2_b   = (const float*)d_in[19];
    float* out = (float*)d_out;
    int write_raw = (out_size >= 2 * R_ * B_) ? 1 : 0;

    cudaFuncSetAttribute(k_weff, cudaFuncAttributeMaxDynamicSharedMemorySize, KW_SMEM_);

    k_head<<<R_, 256>>>(pref, wm1_w, wm1_b, wm2_w, wm2_b,
                        ray0_w, ray0_b, ray2_w, ray2_b,
                        fc2_w, fc2_b, b1_w, b1_b, b2_w, b2_b);
    k_weff<<<dim3(F_ / 8, NSEG_), 256, KW_SMEM_>>>(fc1_w, fc1_b);
    k_wx<<<dim3(8, 16), 128>>>(base_w, base_b);
    k_out<<<B_ / 16, 256>>>(x, out, write_raw);   // #4 -> profiled
}

// round 14
// speedup vs baseline: 1.1141x; 1.0111x over previous
#include <cuda_runtime.h>
#include <cmath>

// Problem constants
#define B_    4096
#define IN_   1024
#define F_    512
#define HID_  128
#define D_    128
#define RH_   64
#define C_    10
#define R_    16
#define CH_   1280   // C_*HID_
#define NSEG_ 8
#define CHSEG_ 160   // CH_/NSEG_
#define STG_  5      // cp.async pipeline stages
#define KW_SMEM_ ((2560 + STG_ * 4096) * 4)   // 92160 bytes
#define KO_SMEM_ ((16 * 257 + 256 * 16 + 32 * 16 * 17) * 4)  // 67648 bytes

// ---------------- device scratch ----------------
__device__ __align__(256) float g_rv[R_][D_];
__device__ __align__(256) float g_P[CH_][R_];            // P[ch][r] = w[r,c]*W2[r,h]
__device__ __align__(256) float g_WeffP[NSEG_][R_][F_];  // k_weff partials (incl. bias)
__device__ __align__(256) float g_WxT[IN_][R_];          // [i][r], atomic-accumulated
__device__ __align__(256) float g_cst[R_];               // beff + Weff·base_b (atomics)

// ---------------- helpers ----------------
__device__ __forceinline__ unsigned long long pk2(float a, float b) {
    unsigned long long r;
    asm("mov.b64 %0, {%1,%2};" : "=l"(r) : "f"(a), "f"(b));
    return r;
}
__device__ __forceinline__ void upk2(unsigned long long v, float& a, float& b) {
    asm("mov.b64 {%0,%1}, %2;" : "=f"(a), "=f"(b) : "l"(v));
}
#define FMA2(acc, a, b) asm("fma.rn.f32x2 %0, %1, %2, %0;" : "+l"(acc) : "l"(a), "l"(b))

__device__ __forceinline__ unsigned smem_u32(const void* p) {
    return (unsigned)__cvta_generic_to_shared(p);
}
__device__ __forceinline__ void cp16(unsigned dst, const void* src) {
    asm volatile("cp.async.cg.shared.global [%0], [%1], 16;" :: "r"(dst), "l"(src) : "memory");
}

// ============ k_head: fused w, r1, rv, W2, b1, beff->cst, P; zero WxT ============
__global__ void __launch_bounds__(256) k_head(
    const float* __restrict__ pref,
    const float* __restrict__ wm1_w, const float* __restrict__ wm1_b,
    const float* __restrict__ wm2_w, const float* __restrict__ wm2_b,
    const float* __restrict__ ray0_w, const float* __restrict__ ray0_b,
    const float* __restrict__ ray2_w, const float* __restrict__ ray2_b,
    const float* __restrict__ fc2_w, const float* __restrict__ fc2_b,
    const float* __restrict__ b1_w,  const float* __restrict__ b1_b,
    const float* __restrict__ b2_w,  const float* __restrict__ b2_b) {
    int r = blockIdx.x;
    int t = threadIdx.x;
    int warp = t >> 5, lane = t & 31;
    __shared__ float sh[16];
    __shared__ float sw[C_];
    __shared__ float sinv;
    __shared__ float sr1[RH_];
    __shared__ __align__(16) float srv[D_];
    __shared__ __align__(16) float sW2[HID_];
    __shared__ __align__(16) float sb1[HID_];
    __shared__ float sb0[HID_], sbb[HID_], sb2r[D_];

    // zero g_WxT for this call (graph replay safe)
    for (int z = r * 256 + t; z < IN_ * R_; z += 16 * 256)
        ((float*)g_WxT)[z] = 0.f;

    float p0 = __ldg(pref + 2 * r), p1 = __ldg(pref + 2 * r + 1);
    if (t < 16) {
        float a = p0 * __ldg(wm1_w + t * 2) + p1 * __ldg(wm1_w + t * 2 + 1) + __ldg(wm1_b + t);
        sh[t] = a > 0.f ? a : 0.f;
    }
    __syncthreads();
    if (t < C_) {
        float a = __ldg(wm2_b + t);
        #pragma unroll
        for (int j = 0; j < 16; j++) a += sh[j] * __ldg(wm2_w + t * 16 + j);
        sw[t] = 1.f / (1.f + expf(-a));
    }
    __syncthreads();
    if (t == 0) {
        float s = 0.f;
        #pragma unroll
        for (int c = 0; c < C_; c++) s += sw[c];
        sinv = 1.f / s;
    }
    __syncthreads();
    if (t < C_) sw[t] *= sinv;
    __syncthreads();

    if (t < RH_) {
        float a = 0.f;
        #pragma unroll
        for (int c = 0; c < C_; c++) {
            float2 rw = __ldg((const float2*)(ray0_w + (c * RH_ + t) * 2));
            a += sw[c] * (p0 * rw.x + p1 * rw.y + __ldg(ray0_b + c * RH_ + t));
        }
        sr1[t] = a > 0.f ? a : 0.f;
    } else if (t < 64 + D_) {
        int d = t - 64;
        float b = 0.f;
        #pragma unroll
        for (int c = 0; c < C_; c++) b += sw[c] * __ldg(ray2_b + c * D_ + d);
        sb2r[d] = b;
    }
    __syncthreads();

    // rv: 8 warps x 16 oi, lanes over h
    {
        float r1a = sr1[lane], r1b = sr1[lane + 32];
        float acc[16];
        #pragma unroll
        for (int oi = 0; oi < 16; oi++) acc[oi] = 0.f;
        #pragma unroll
        for (int c = 0; c < C_; c++) {
            float wc = sw[c];
            #pragma unroll
            for (int oi = 0; oi < 16; oi++) {
                int o = warp * 16 + oi;
                const float* row = ray2_w + ((size_t)(c * D_ + o)) * RH_;
                acc[oi] += wc * (__ldg(row + lane) * r1a + __ldg(row + lane + 32) * r1b);
            }
        }
        #pragma unroll
        for (int oi = 0; oi < 16; oi++) {
            float s = acc[oi];
            #pragma unroll
            for (int off = 16; off > 0; off >>= 1) s += __shfl_down_sync(0xffffffffu, s, off);
            if (lane == 0) {
                int o = warp * 16 + oi;
                float v = s + sb2r[o];
                srv[o] = v;
                g_rv[r][o] = v;
            }
        }
    }
    if (t < 128) {
        float b = 0.f;
        #pragma unroll
        for (int c = 0; c < C_; c++) b += sw[c] * __ldg(fc2_b + c * HID_ + t);
        sb0[t] = b;
    } else {
        int o = t - 128;
        float b = 0.f;
        #pragma unroll
        for (int c = 0; c < C_; c++) b += sw[c] * __ldg(b1_b + c * HID_ + o);
        sbb[o] = b;
    }
    __syncthreads();

    // W2 (warps 0-3) and b1 (warps 4-7): warp handles 32 o's
    {
        int kind = warp >> 2;
        int ob = (warp & 3) * 32;
        const float* Wc = kind ? b1_w : fc2_w;
        float4 rv4 = *(const float4*)&srv[lane * 4];
        float acc[32];
        #pragma unroll
        for (int oi = 0; oi < 32; oi++) acc[oi] = 0.f;
        #pragma unroll
        for (int c = 0; c < C_; c++) {
            float wc = sw[c];
            #pragma unroll
            for (int oi = 0; oi < 32; oi++) {
                int o = ob + oi;
                float4 v = __ldg((const float4*)(Wc + ((size_t)(c * HID_ + o)) * D_) + lane);
                acc[oi] += wc * (v.x * rv4.x + v.y * rv4.y + v.z * rv4.z + v.w * rv4.w);
            }
        }
        #pragma unroll
        for (int oi = 0; oi < 32; oi++) {
            float s = acc[oi];
            #pragma unroll
            for (int off = 16; off > 0; off >>= 1) s += __shfl_down_sync(0xffffffffu, s, off);
            if (lane == 0) {
                int o = ob + oi;
                if (kind) sb1[o] = s + sbb[o]; else sW2[o] = s + sb0[o];
            }
        }
    }
    __syncthreads();

    if (warp == 0) {
        float4 rv4 = *(const float4*)&srv[lane * 4];
        float acc = 0.f;
        #pragma unroll
        for (int c = 0; c < C_; c++) {
            float wc = sw[c];
            float4 bw = __ldg((const float4*)(b2_w + c * D_) + lane);
            acc += wc * (bw.x * rv4.x + bw.y * rv4.y + bw.z * rv4.z + bw.w * rv4.w);
            if (lane == 0) acc += wc * __ldg(b2_b + c);
        }
        float4 w24 = *(const float4*)&sW2[lane * 4];
        float4 b14 = *(const float4*)&sb1[lane * 4];
        acc += w24.x * b14.x + w24.y * b14.y + w24.z * b14.z + w24.w * b14.w;
        #pragma unroll
        for (int off = 16; off > 0; off >>= 1) acc += __shfl_down_sync(0xffffffffu, acc, off);
        if (lane == 0) g_cst[r] = acc;   // beff; k_wx atomically adds Weff·base_b
    }
    for (int ch = t; ch < CH_; ch += 256)
        g_P[ch][r] = sw[ch >> 7] * sW2[ch & 127];
}

// ============ k_weff v7: cp.async pipeline, strength-reduced addressing ========
extern __shared__ float dsm_[];
__global__ void __launch_bounds__(256, 2) k_weff(const float* __restrict__ fc1_w,
                                                 const float* __restrict__ fc1_b) {
    float* sP   = dsm_;          // 2560 floats (160 ch x 16 r)
    float* sbuf = dsm_ + 2560;   // STG_ x 4096 floats (4 ch x 8 f x 128 d)
    int seg = blockIdx.y;
    int t = threadIdx.x;
    int warp = t >> 5, lane = t & 31;

    for (int idx = t; idx < CHSEG_ * 16; idx += 256)
        sP[idx] = ((const float*)g_P[seg * CHSEG_])[idx];

    const float4* gbase = (const float4*)fc1_w
        + (size_t)(seg * CHSEG_) * 16384u + (size_t)(blockIdx.x * 8 + warp) * 32u + lane;
    unsigned dstbase = smem_u32(sbuf) + (unsigned)((warp * 32 + lane) * 16);
    const float4* myb = (const float4*)sbuf + (warp * 32 + lane);  // + slot*1024 + q*256

    __syncthreads();   // sP visible to all warps (the ONLY cross-warp data)

    #pragma unroll
    for (int s = 0; s < STG_ - 1; s++) {
        #pragma unroll
        for (int q = 0; q < 4; q++)
            cp16(dstbase + (unsigned)(s * 16384 + q * 4096),
                 gbase + (size_t)(s * 4 + q) * 16384u);
        asm volatile("cp.async.commit_group;" ::: "memory");
    }

    unsigned long long acc[4][8];
    #pragma unroll
    for (int j = 0; j < 4; j++)
        #pragma unroll
        for (int rp = 0; rp < 8; rp++) acc[j][rp] = 0ull;

    const float4* gpre = gbase + (size_t)(STG_ - 1) * 4 * 16384u;
    const ulonglong2* pPtr = (const ulonglong2*)sP;

    #pragma unroll 1
    for (int g = 0; g < (CHSEG_ / 4) / STG_; g++) {   // 8 outer groups
        #pragma unroll
        for (int j5 = 0; j5 < STG_; j5++) {           // slot = j5 (compile-time)
            int i = g * STG_ + j5;
            asm volatile("cp.async.wait_group %0;" :: "n"(STG_ - 2) : "memory");
            const float4* bq = myb + j5 * 1024;
            #pragma unroll
            for (int q = 0; q < 4; q++) {
                float4 v = bq[q * 256];
                ulonglong2 pA = pPtr[q * 4 + 0], pB = pPtr[q * 4 + 1];
                ulonglong2 pC = pPtr[q * 4 + 2], pD = pPtr[q * 4 + 3];
                unsigned long long u0 = pk2(v.x, v.x);
                unsigned long long u1 = pk2(v.y, v.y);
                unsigned long long u2 = pk2(v.z, v.z);
                unsigned long long u3 = pk2(v.w, v.w);
                FMA2(acc[0][0], u0, pA.x); FMA2(acc[0][1], u0, pA.y);
                FMA2(acc[0][2], u0, pB.x); FMA2(acc[0][3], u0, pB.y);
                FMA2(acc[0][4], u0, pC.x); FMA2(acc[0][5], u0, pC.y);
                FMA2(acc[0][6], u0, pD.x); FMA2(acc[0][7], u0, pD.y);
                FMA2(acc[1][0], u1, pA.x); FMA2(acc[1][1], u1, pA.y);
                FMA2(acc[1][2], u1, pB.x); FMA2(acc[1][3], u1, pB.y);
                FMA2(acc[1][4], u1, pC.x); FMA2(acc[1][5], u1, pC.y);
                FMA2(acc[1][6], u1, pD.x); FMA2(acc[1][7], u1, pD.y);
                FMA2(acc[2][0], u2, pA.x); FMA2(acc[2][1], u2, pA.y);
                FMA2(acc[2][2], u2, pB.x); FMA2(acc[2][3], u2, pB.y);
                FMA2(acc[2][4], u2, pC.x); FMA2(acc[2][5], u2, pC.y);
                FMA2(acc[2][6], u2, pD.x); FMA2(acc[2][7], u2, pD.y);
                FMA2(acc[3][0], u3, pA.x); FMA2(acc[3][1], u3, pA.y);
                FMA2(acc[3][2], u3, pB.x); FMA2(acc[3][3], u3, pB.y);
                FMA2(acc[3][4], u3, pC.x); FMA2(acc[3][5], u3, pC.y);
                FMA2(acc[3][6], u3, pD.x); FMA2(acc[3][7], u3, pD.y);
            }
            pPtr += 16;
            if (i < (CHSEG_ / 4) - (STG_ - 1)) {
                const unsigned pslot = (unsigned)(((j5 + STG_ - 1) % STG_) * 16384);
                #pragma unroll
                for (int q = 0; q < 4; q++)
                    cp16(dstbase + pslot + (unsigned)(q * 4096), gpre + q * 16384);
            }
            gpre += 65536;
            asm volatile("cp.async.commit_group;" ::: "memory");
        }
    }
    asm volatile("cp.async.wait_group 0;" ::: "memory");

    // fused fc1_b bias: lane covers ch = lane, lane+32, ... (5 iters)
    int f = blockIdx.x * 8 + warp;
    unsigned long long bacc[8];
    #pragma unroll
    for (int rp = 0; rp < 8; rp++) bacc[rp] = 0ull;
    #pragma unroll
    for (int it = 0; it < CHSEG_ / 32; it++) {
        int chl = it * 32 + lane;
        float bv = __ldg(fc1_b + (size_t)(seg * CHSEG_ + chl) * 512u + f);
        unsigned long long vv = pk2(bv, bv);
        const ulonglong2* pp = (const ulonglong2*)(sP + chl * 16);
        ulonglong2 pA = pp[0], pB = pp[1], pC = pp[2], pD = pp[3];
        FMA2(bacc[0], vv, pA.x); FMA2(bacc[1], vv, pA.y);
        FMA2(bacc[2], vv, pB.x); FMA2(bacc[3], vv, pB.y);
        FMA2(bacc[4], vv, pC.x); FMA2(bacc[5], vv, pC.y);
        FMA2(bacc[6], vv, pD.x); FMA2(bacc[7], vv, pD.y);
    }

    int d0 = lane * 4;
    float accr[16];
    #pragma unroll
    for (int rp = 0; rp < 8; rp++) {
        float a0, a1; upk2(bacc[rp], a0, a1);
        accr[2 * rp] = a0; accr[2 * rp + 1] = a1;
    }
    #pragma unroll
    for (int j = 0; j < 4; j++) {
        #pragma unroll
        for (int rp = 0; rp < 8; rp++) {
            float a0, a1; upk2(acc[j][rp], a0, a1);
            accr[2 * rp]     += a0 * g_rv[2 * rp][d0 + j];
            accr[2 * rp + 1] += a1 * g_rv[2 * rp + 1][d0 + j];
        }
    }
    #pragma unroll
    for (int off = 16; off > 0; off >>= 1)
        #pragma unroll
        for (int r = 0; r < 16; r++)
            accr[r] += __shfl_down_sync(0xffffffffu, accr[r], off);
    if (lane == 0) {
        #pragma unroll
        for (int r = 0; r < 16; r++) g_WeffP[seg][r][f] = accr[r];
    }
}

// ============ k_wx: sum 8 planes -> fold base_w -> atomic Wx; cst inline ======
__global__ void __launch_bounds__(128) k_wx(const float* __restrict__ base_w,
                                            const float* __restrict__ base_b) {
    __shared__ __align__(16) float sW[32][16];
    int t = threadIdx.x;
    int f0 = blockIdx.y * 32;
    for (int idx = t; idx < 32 * 16; idx += 128) {
        int ff = idx >> 4, r = idx & 15;
        float s = 0.f;
        #pragma unroll
        for (int sg = 0; sg < NSEG_; sg++) s += g_WeffP[sg][r][f0 + ff];
        sW[ff][r] = s;
    }
    __syncthreads();
    if (blockIdx.x == 0) {
        int r = t >> 3, fq = (t & 7) * 4;
        float p = 0.f;
        #pragma unroll
        for (int j = 0; j < 4; j++) p += sW[fq + j][r] * __ldg(base_b + f0 + fq + j);
        atomicAdd(&g_cst[r], p);
    }
    int i = blockIdx.x * 128 + t;
    unsigned long long acc[8];
    #pragma unroll
    for (int rp = 0; rp < 8; rp++) acc[rp] = 0ull;
    #pragma unroll 4
    for (int ff = 0; ff < 32; ff++) {
        float bw = __ldg(base_w + (size_t)(f0 + ff) * IN_ + i);
        unsigned long long b2 = pk2(bw, bw);
        const unsigned long long* pw = (const unsigned long long*)sW[ff];
        #pragma unroll
        for (int rp = 0; rp < 8; rp++) {
            unsigned long long tt = pw[rp];
            FMA2(acc[rp], b2, tt);
        }
    }
    #pragma unroll
    for (int rp = 0; rp < 8; rp++) {
        float a, b; upk2(acc[rp], a, b);
        atomicAdd(&g_WxT[i][2 * rp], a);
        atomicAdd(&g_WxT[i][2 * rp + 1], b);
    }
}

// ============ k_out v6: 512 thr, 16 b, 4 chunks of 256 i, dynamic smem ========
extern __shared__ float osm_[];
__global__ void __launch_bounds__(512) k_out(const float* __restrict__ x,
                                             float* __restrict__ out, int write_raw) {
    float* sx  = osm_;                      // [16][257]
    float* swt = osm_ + 16 * 257;           // [256][16]
    float* sp  = swt + 256 * 16;            // [32][16][17]
    int t = threadIdx.x;
    int bl = t & 15, part = t >> 4;         // 32 parts
    int bbase = blockIdx.x * 16;

    unsigned long long acc[8];
    #pragma unroll
    for (int rp = 0; rp < 8; rp++) acc[rp] = 0ull;

    for (int c = 0; c < 4; c++) {
        int i0 = c * 256;
        #pragma unroll
        for (int k = 0; k < 8; k++) {
            int idx = k * 512 + t;
            int b = idx >> 8, i = idx & 255;
            sx[b * 257 + i] = __ldg(x + (size_t)(bbase + b) * IN_ + i0 + i);
        }
        #pragma unroll
        for (int k = 0; k < 8; k++)
            swt[k * 512 + t] = ((const float*)g_WxT)[i0 * 16 + k * 512 + t];
        __syncthreads();

        #pragma unroll
        for (int ii = 0; ii < 8; ii++) {
            int i = part * 8 + ii;
            float xv = sx[bl * 257 + i];
            unsigned long long ux = pk2(xv, xv);
            const ulonglong2* w = (const ulonglong2*)(swt + i * 16);
            ulonglong2 wA = w[0], wB = w[1], wC = w[2], wD = w[3];
            FMA2(acc[0], ux, wA.x); FMA2(acc[1], ux, wA.y);
            FMA2(acc[2], ux, wB.x); FMA2(acc[3], ux, wB.y);
            FMA2(acc[4], ux, wC.x); FMA2(acc[5], ux, wC.y);
            FMA2(acc[6], ux, wD.x); FMA2(acc[7], ux, wD.y);
        }
        __syncthreads();
    }

    // write partials: sp[(part*16+bl)*17 + k]
    float* myp = sp + (size_t)(part * 16 + bl) * 17;
    #pragma unroll
    for (int rp = 0; rp < 8; rp++) {
        float a, b; upk2(acc[rp], a, b);
        myp[2 * rp] = a;
        myp[2 * rp + 1] = b;
    }
    __syncthreads();

    if (t < 256) {
        int b = t >> 4, r = t & 15;
        float s = 0.f;
        #pragma unroll
        for (int p = 0; p < 32; p++) s += sp[(size_t)(p * 16 + b) * 17 + r];
        float v = s + g_cst[r];
        out[r * B_ + bbase + b] = 1.f / (1.f + expf(-v));
        if (write_raw) out[R_ * B_ + r * B_ + bbase + b] = v;
    }
}

// ---------------- launcher ----------------
extern "C" void kernel_launch(void* const* d_in, const int* in_sizes, int n_in,
                              void* d_out, int out_size) {
    const float* x      = (const float*)d_in[0];
    const float* pref   = (const float*)d_in[1];
    const float* base_w = (const float*)d_in[2];
    const float* base_b = (const float*)d_in[3];
    const float* wm1_w  = (const float*)d_in[4];
    const float* wm1_b  = (const float*)d_in[5];
    const float* wm2_w  = (const float*)d_in[6];
    const float* wm2_b  = (const float*)d_in[7];
    const float* ray0_w = (const float*)d_in[8];
    const float* ray0_b = (const float*)d_in[9];
    const float* ray2_w = (const float*)d_in[10];
    const float* ray2_b = (const float*)d_in[11];
    const float* fc1_w  = (const float*)d_in[12];
    const float* fc1_b  = (const float*)d_in[13];
    const float* b1_w   = (const float*)d_in[14];
    const float* b1_b   = (const float*)d_in[15];
    const float* fc2_w  = (const float*)d_in[16];
    const float* fc2_b  = (const float*)d_in[17];
    const float* b2_w   = (const float*)d_in[18];
    const float* b2_b   = (const float*)d_in[19];
    float* out = (float*)d_out;
    int write_raw = (out_size >= 2 * R_ * B_) ? 1 : 0;

    cudaFuncSetAttribute(k_weff, cudaFuncAttributeMaxDynamicSharedMemorySize, KW_SMEM_);
    cudaFuncSetAttribute(k_out, cudaFuncAttributeMaxDynamicSharedMemorySize, KO_SMEM_);

    k_head<<<R_, 256>>>(pref, wm1_w, wm1_b, wm2_w, wm2_b,
                        ray0_w, ray0_b, ray2_w, ray2_b,
                        fc2_w, fc2_b, b1_w, b1_b, b2_w, b2_b);
    k_weff<<<dim3(F_ / 8, NSEG_), 256, KW_SMEM_>>>(fc1_w, fc1_b);
    k_wx<<<dim3(8, 16), 128>>>(base_w, base_b);
    k_out<<<B_ / 16, 512, KO_SMEM_>>>(x, out, write_raw);   // #4 -> profiled
}